// round 14
// baseline (speedup 1.0000x reference)
#include <cuda_runtime.h>
#include <cstdint>
#include <math.h>

// Problem constants (fixed by setup_inputs)
#define B_   32
#define C_   24
#define H_   28
#define W_   28
#define OH_  24
#define OW_  24
#define KHW  25
#define CF_  600           // C * KH * KW
#define HN_  128
#define T_   96
#define NPIX (OH_*OW_)     // 576

__device__ float d_patch [B_ * NPIX * CF_];   // [B, OH, OW, Cf]  raw unfolded input
__device__ float d_patchs[B_ * NPIX * CF_];   // prw = -ln2 / w  (negative)
__device__ int   d_spikes[B_ * NPIX * T_];    // [B, OH, OW, T]

#define NWARP_TOT   ((uint32_t)B_ * T_ * NPIX)    // 1,769,472
#define NWARP_THIRD (NWARP_TOT / 3u)              // 589,824

// ---------------------------------------------------------------------------
// Threefry-2x32-20, key (0, 42). Partitionable path: x = (0, i), out = o0^o1.
// Half the rotates are mul-pair form: rotl(x,r) = mul.lo(x,2^r) | umulhi(x,2^r),
// with 2^r as RUNTIME kernel args (m13..m16) so ptxas must emit IMAD (FMA pipe)
// instead of SHF (saturated ALU pipe). The OR is folded into the round XOR as
// one 3-input LOP3 (lut 0x56 = (a|b)^c). Bit-exact integer identities.
// ---------------------------------------------------------------------------
__device__ __forceinline__ uint32_t lop3_or_xor(uint32_t a, uint32_t b,
                                                uint32_t c) {
    uint32_t d;
    asm("lop3.b32 %0, %1, %2, %3, 0x56;" : "=r"(d) : "r"(a), "r"(b), "r"(c));
    return d;
}

__device__ __forceinline__ uint32_t threefry_bits(uint32_t i,
        uint32_t m13, uint32_t m26, uint32_t m17, uint32_t m16) {
    const uint32_t ks1 = 42u;
    const uint32_t ks2 = 0x1BD11BF0u;   // 0 ^ 42 ^ 0x1BD11BDA
    uint32_t x0 = 0u;
    uint32_t x1 = i + ks1;
    // SHF-form round (ALU rotate)
#define TF_RND(r) { x0 += x1; x1 = __funnelshift_l(x1, x1, (r)) ^ x0; }
    // mul-form round (FMA-pipe rotate via runtime multiplier)
#define TF_RNDM(m) { x0 += x1;                                            \
        uint32_t lo_ = x1 * (m);                                          \
        uint32_t hi_ = __umulhi(x1, (m));                                 \
        x1 = lop3_or_xor(lo_, hi_, x0); }
    // Group A: rotations 13,15,26,6  (13 and 26 converted)
#define TF_GRP_A  TF_RNDM(m13) TF_RND(15) TF_RNDM(m26) TF_RND(6)
    // Group B: rotations 17,29,16,24 (17 and 16 converted)
#define TF_GRP_B  TF_RNDM(m17) TF_RND(29) TF_RNDM(m16) TF_RND(24)

    TF_GRP_A
    x0 += ks1;  x1 += ks2 + 1u;
    TF_GRP_B
    x0 += ks2;  x1 += 2u;
    TF_GRP_A
    x1 += ks1 + 3u;
    TF_GRP_B
    x0 += ks1;  x1 += ks2 + 4u;
    TF_GRP_A
    x0 += ks2;  x1 += 5u;
#undef TF_RND
#undef TF_RNDM
#undef TF_GRP_A
#undef TF_GRP_B
    return x0 ^ x1;
}

// u bits: (bits>>9)|0x3F800000 == umulhi(bits,2^23)+0x3F800000 (bit-exact).
__device__ __forceinline__ float u_from_bits(uint32_t bits) {
    uint32_t ub = __umulhi(bits, 1u << 23) + 0x3F800000u;
    return __uint_as_float(ub) - 1.0f;
}

// ---------------------------------------------------------------------------
// Exact E = -log(u): sign-flipped cephes poly (bit-exact verify path).
// ---------------------------------------------------------------------------
__device__ __forceinline__ float exp_draw(uint32_t bits) {
    float u = u_from_bits(bits);
    uint32_t ix = __float_as_uint(u);
    ix -= 0x3F3504F3u;                       // sqrt(0.5) bits
    int   e  = (int)ix >> 23;
    float m  = __uint_as_float((ix & 0x007FFFFFu) + 0x3F3504F3u);
    float f  = m - 1.0f;
    float z  = f * f;
    float pn = -7.0376836292e-2f;
    pn = fmaf(pn, f,  1.1514610310e-1f);
    pn = fmaf(pn, f, -1.1676998740e-1f);
    pn = fmaf(pn, f,  1.2420140846e-1f);
    pn = fmaf(pn, f, -1.4249322787e-1f);
    pn = fmaf(pn, f,  1.6668057665e-1f);
    pn = fmaf(pn, f, -2.0000714765e-1f);
    pn = fmaf(pn, f,  2.4999993993e-1f);
    pn = fmaf(pn, f, -3.3333331174e-1f);
    float fe = (float)e;
    float q  = fmaf(z * f, pn, fmaf(fe, 2.12194440e-4f, 0.5f * z));
    q = q - f;
    return fmaf(fe, -0.693359375f, q);       // E = -log(u)
}

// ---------------------------------------------------------------------------
// Kernel 1: unfold; writes raw patch AND prw = -ln2/w.
// ---------------------------------------------------------------------------
__global__ void unfold_kernel(const float* __restrict__ input) {
    int row = blockIdx.x;                 // b*NPIX + p
    int b = row / NPIX;
    int p = row % NPIX;
    int x = p / OW_, y = p % OW_;
    float* dst  = d_patch  + (size_t)row * CF_;
    float* dsts = d_patchs + (size_t)row * CF_;
    const float* src = input + ((size_t)b * C_ * H_ + (size_t)x) * W_ + y;
    for (int m = threadIdx.x; m < CF_; m += blockDim.x) {
        int c = m / KHW, k = m % KHW;
        int i = k / 5, j = k % 5;
        float v = src[(c * H_ + i) * W_ + j];
        dst[m]  = v;
        dsts[m] = __fdividef(-0.69314718056f, v);   // prw < 0 (approx; margin covers)
    }
}

// ---------------------------------------------------------------------------
// Kernel 2: spike sampling. Fast path: q = lg2(u) * prw = E/w (argmin),
// index packed into q's low 10 bits so fminf does compare+select+tie-break.
// Margin test vs packed second-best; on failure, exact rescan (bit-exact).
// ---------------------------------------------------------------------------
__global__ void __launch_bounds__(256) spike_kernel(uint32_t warp_off,
        uint32_t m13, uint32_t m26, uint32_t m17, uint32_t m16) {
    uint32_t gwarp = warp_off +
        (uint32_t)((blockIdx.x * blockDim.x + threadIdx.x) >> 5);
    int lane = threadIdx.x & 31;
    if (gwarp >= NWARP_TOT) return;

    uint32_t b = gwarp / (T_ * NPIX);
    uint32_t r_ = gwarp % (T_ * NPIX);
    uint32_t t = r_ / NPIX;
    uint32_t p = r_ % NPIX;

    uint32_t base = gwarp * (uint32_t)CF_;
    const float*  prow  = d_patchs + ((size_t)b * NPIX + p) * CF_;
    const float2* prow2 = reinterpret_cast<const float2*>(prow);

    float s1 = INFINITY, s2 = INFINITY;   // packed top-2 (smallest q wins)

    // q > 0 always (L<0, prw<0); u==0 -> q=+inf -> packed NaN -> fminf drops it
#define FAST_ELEM(prwv, iv, cv) {                                            \
        uint32_t bits = threefry_bits((iv), m13, m26, m17, m16);             \
        float u = u_from_bits(bits);                                         \
        float L = __log2f(u);                                                \
        float q = L * (prwv);                                                \
        float qp = __uint_as_float(                                          \
            (__float_as_uint(q) & 0xFFFFFC00u) | (uint32_t)(cv));            \
        s2 = fminf(s2, fmaxf(s1, qp));                                       \
        s1 = fminf(s1, qp);                                                  \
    }

    uint32_t iA = base + (uint32_t)(2 * lane);
    int cA = 2 * lane;
    #pragma unroll
    for (int kk = 0; kk < 4; ++kk) {
        float2 wA = prow2[kk * 64 + lane];
        float2 wB = prow2[kk * 64 + 32 + lane];
        FAST_ELEM(wA.x, iA,       cA);
        FAST_ELEM(wA.y, iA + 1u,  cA + 1);
        FAST_ELEM(wB.x, iA + 64u, cA + 64);
        FAST_ELEM(wB.y, iA + 65u, cA + 65);
        iA += 128u;
        cA += 128;
    }
    {   // slot 8: c = 512 + 2*lane
        float2 w = prow2[256 + lane];
        FAST_ELEM(w.x, iA,      cA);
        FAST_ELEM(w.y, iA + 1u, cA + 1);
    }
    if (lane < 12) {   // tail: c = 576 + 2*lane
        int c = 576 + 2 * lane;
        float2 w = prow2[288 + lane];
        FAST_ELEM(w.x, base + (uint32_t)c,      c);
        FAST_ELEM(w.y, base + (uint32_t)c + 1u, c + 1);
    }
#undef FAST_ELEM

    // warp top-2 min reduce (packed => tie-break automatic)
    #pragma unroll
    for (int off = 16; off; off >>= 1) {
        float o1 = __shfl_down_sync(0xffffffffu, s1, off);
        float o2 = __shfl_down_sync(0xffffffffu, s2, off);
        s2 = fminf(fminf(s2, o2), fmaxf(s1, o1));
        s1 = fminf(s1, o1);
    }

    int safe = 0;
    int widx = 0;
    if (lane == 0) {
        uint32_t i1 = __float_as_uint(s1) & 1023u;
        float prw1 = -prow[i1];                      // = ln2/w1 > 0
        float delta = fmaf(2.6e-7f, prw1,
                      fmaf(1.6e-4f, s1 + s2, 2.0e-5f));
        safe = ((s2 - s1) > delta) ? 1 : 0;
        widx = (int)i1;
    }
    safe = __shfl_sync(0xffffffffu, safe, 0);

    if (!safe) {
        // exact rescan (bit-exact decider), rolled loop
        const float* wrow = d_patch + ((size_t)b * NPIX + p) * CF_;
        float bw = 0.0f, bE = 1.0f;
        int   idx = 0;
        for (int j = 0; j < 19; ++j) {
            int c = lane + 32 * j;
            if (c < CF_) {
                uint32_t bits = threefry_bits(base + (uint32_t)c,
                                              m13, m26, m17, m16);
                float E = exp_draw(bits);
                float w = wrow[c];
                if (w * bE > bw * E) { bw = w; bE = E; idx = c; }
            }
        }
        #pragma unroll
        for (int off = 16; off; off >>= 1) {
            float ow = __shfl_down_sync(0xffffffffu, bw, off);
            float oE = __shfl_down_sync(0xffffffffu, bE, off);
            int   oi = __shfl_down_sync(0xffffffffu, idx, off);
            float lhs = ow * bE, rhs = bw * oE;
            if (lhs > rhs || (lhs == rhs && oi < idx)) { bw = ow; bE = oE; idx = oi; }
        }
        if (lane == 0) widx = idx;
    }

    if (lane == 0)
        d_spikes[((size_t)b * NPIX + p) * T_ + t] = widx;
}

// ---------------------------------------------------------------------------
// Kernel 3: normalized recurrence, one warp per (b, pixel), g[128] in regs.
// ---------------------------------------------------------------------------
__global__ void recur_kernel(const float* __restrict__ weights,
                             const float* __restrict__ eps_xy,
                             const float* __restrict__ eps0p,
                             const float* __restrict__ eps_t,
                             const float* __restrict__ h_init,
                             float* __restrict__ out) {
    int gwarp = (blockIdx.x * blockDim.x + threadIdx.x) >> 5;
    int lane  = threadIdx.x & 31;
    if (gwarp >= B_ * NPIX) return;
    int b = gwarp / NPIX, p = gwarp % NPIX;

    float4 g = reinterpret_cast<const float4*>(h_init)[lane];
    float eps0 = eps0p[0];
    const float* epsrow = eps_xy + (size_t)p * KHW;
    const int*   srow   = d_spikes + (size_t)gwarp * T_;

    for (int t = 0; t < T_; ++t) {
        int s = srow[t];
        float4 w = reinterpret_cast<const float4*>(weights + (size_t)s * HN_)[lane];
        float4 wg = make_float4(w.x * g.x, w.y * g.y, w.z * g.z, w.w * g.w);
        float sum = (wg.x + wg.y) + (wg.z + wg.w);
        #pragma unroll
        for (int off = 16; off; off >>= 1)
            sum += __shfl_xor_sync(0xffffffffu, sum, off);

        float eps_sub = epsrow[s % KHW] * (eps_t[t] * eps0);
        float factor  = eps_sub / sum;
        if (!isfinite(factor)) factor = 0.0f;
        float rr = 1.0f / (1.0f + eps_sub);
        g.x = (g.x + wg.x * factor) * rr;
        g.y = (g.y + wg.y * factor) * rr;
        g.z = (g.z + wg.z * factor) * rr;
        g.w = (g.w + wg.w * factor) * rr;
    }

    float* o = out + ((size_t)b * HN_) * NPIX + p;
    o[(lane * 4 + 0) * NPIX] = g.x;
    o[(lane * 4 + 1) * NPIX] = g.y;
    o[(lane * 4 + 2) * NPIX] = g.z;
    o[(lane * 4 + 3) * NPIX] = g.w;
}

// ---------------------------------------------------------------------------
extern "C" void kernel_launch(void* const* d_in, const int* in_sizes, int n_in,
                              void* d_out, int out_size) {
    const float* input   = (const float*)d_in[0];  // [B,C,H,W]
    const float* eps_xy  = (const float*)d_in[1];  // [OH,OW,KH,KW]
    const float* eps0    = (const float*)d_in[2];  // [1]
    const float* eps_t   = (const float*)d_in[3];  // [T]
    const float* weights = (const float*)d_in[4];  // [Cf,Hn]
    const float* h_init  = (const float*)d_in[5];  // [Hn]
    float* out = (float*)d_out;                    // [B,Hn,OH,OW]

    unfold_kernel<<<B_ * NPIX, 256>>>(input);
    // 3 spike launches; rotation multipliers passed at runtime so ptxas
    // cannot strength-reduce the IMAD rotates back to SHF.
    for (uint32_t s = 0; s < 3; ++s)
        spike_kernel<<<NWARP_THIRD / 8, 256>>>(s * NWARP_THIRD,
                                               1u << 13, 1u << 26,
                                               1u << 17, 1u << 16);
    recur_kernel<<<(B_ * NPIX * 32) / 256, 256>>>(weights, eps_xy, eps0,
                                                  eps_t, h_init, out);
}

// round 15
// speedup vs baseline: 1.0781x; 1.0781x over previous
#include <cuda_runtime.h>
#include <cstdint>
#include <math.h>

// Problem constants (fixed by setup_inputs)
#define B_   32
#define C_   24
#define H_   28
#define W_   28
#define OH_  24
#define OW_  24
#define KHW  25
#define CF_  600           // C * KH * KW
#define HN_  128
#define T_   96
#define NPIX (OH_*OW_)     // 576

__device__ float d_patch [B_ * NPIX * CF_];   // [B, OH, OW, Cf]  raw unfolded input
__device__ float d_patchs[B_ * NPIX * CF_];   // prw = -ln2 / w  (negative)
__device__ int   d_spikes[B_ * NPIX * T_];    // [B, OH, OW, T]

#define NWARP_TOT  ((uint32_t)B_ * T_ * NPIX)     // 1,769,472
#define NWARP_HALF (NWARP_TOT / 2u)               // 884,736

// ---------------------------------------------------------------------------
// Threefry-2x32-20, key (0, 42). Partitionable path: x = (0, i), out = o0^o1.
// Plain SHF rotate + compiler-scheduled adds: measured-best codegen
// (R8 wide-mul, R13 asm-IMAD adds, R14 runtime-mul rotates all regressed).
// ---------------------------------------------------------------------------
__device__ __forceinline__ uint32_t threefry_bits(uint32_t i) {
    const uint32_t ks1 = 42u;
    const uint32_t ks2 = 0x1BD11BF0u;   // 0 ^ 42 ^ 0x1BD11BDA
    uint32_t x0 = 0u;
    uint32_t x1 = i + ks1;
#define TF_RND(r) { x0 += x1; x1 = __funnelshift_l(x1, x1, (r)) ^ x0; }
    TF_RND(13) TF_RND(15) TF_RND(26) TF_RND(6)
    x0 += ks1;  x1 += ks2 + 1u;
    TF_RND(17) TF_RND(29) TF_RND(16) TF_RND(24)
    x0 += ks2;  x1 += 2u;
    TF_RND(13) TF_RND(15) TF_RND(26) TF_RND(6)
    x1 += ks1 + 3u;
    TF_RND(17) TF_RND(29) TF_RND(16) TF_RND(24)
    x0 += ks1;  x1 += ks2 + 4u;
    TF_RND(13) TF_RND(15) TF_RND(26) TF_RND(6)
    x0 += ks2;  x1 += 5u;
#undef TF_RND
    return x0 ^ x1;
}

// u bits: (bits>>9)|0x3F800000 == umulhi(bits,2^23)+0x3F800000 (bit-exact).
__device__ __forceinline__ float u_from_bits(uint32_t bits) {
    uint32_t ub = __umulhi(bits, 1u << 23) + 0x3F800000u;
    return __uint_as_float(ub) - 1.0f;
}

// ---------------------------------------------------------------------------
// Exact E = -log(u): sign-flipped cephes poly (bit-exact verify path).
// ---------------------------------------------------------------------------
__device__ __forceinline__ float exp_draw(uint32_t bits) {
    float u = u_from_bits(bits);
    uint32_t ix = __float_as_uint(u);
    ix -= 0x3F3504F3u;                       // sqrt(0.5) bits
    int   e  = (int)ix >> 23;
    float m  = __uint_as_float((ix & 0x007FFFFFu) + 0x3F3504F3u);
    float f  = m - 1.0f;
    float z  = f * f;
    float pn = -7.0376836292e-2f;
    pn = fmaf(pn, f,  1.1514610310e-1f);
    pn = fmaf(pn, f, -1.1676998740e-1f);
    pn = fmaf(pn, f,  1.2420140846e-1f);
    pn = fmaf(pn, f, -1.4249322787e-1f);
    pn = fmaf(pn, f,  1.6668057665e-1f);
    pn = fmaf(pn, f, -2.0000714765e-1f);
    pn = fmaf(pn, f,  2.4999993993e-1f);
    pn = fmaf(pn, f, -3.3333331174e-1f);
    float fe = (float)e;
    float q  = fmaf(z * f, pn, fmaf(fe, 2.12194440e-4f, 0.5f * z));
    q = q - f;
    return fmaf(fe, -0.693359375f, q);       // E = -log(u)
}

// ---------------------------------------------------------------------------
// Kernel 1: unfold; writes raw patch AND prw = -ln2/w.
// ---------------------------------------------------------------------------
__global__ void unfold_kernel(const float* __restrict__ input) {
    int row = blockIdx.x;                 // b*NPIX + p
    int b = row / NPIX;
    int p = row % NPIX;
    int x = p / OW_, y = p % OW_;
    float* dst  = d_patch  + (size_t)row * CF_;
    float* dsts = d_patchs + (size_t)row * CF_;
    const float* src = input + ((size_t)b * C_ * H_ + (size_t)x) * W_ + y;
    for (int m = threadIdx.x; m < CF_; m += blockDim.x) {
        int c = m / KHW, k = m % KHW;
        int i = k / 5, j = k % 5;
        float v = src[(c * H_ + i) * W_ + j];
        dst[m]  = v;
        dsts[m] = __fdividef(-0.69314718056f, v);   // prw < 0 (approx; margin covers)
    }
}

// ---------------------------------------------------------------------------
// Kernel 2: spike sampling. Fast path: q = lg2(u) * prw = E/w (argmin),
// index packed into q's low 10 bits so fminf does compare+select+tie-break.
// Margin test vs packed second-best; on failure, exact rescan (bit-exact).
// ---------------------------------------------------------------------------
__global__ void __launch_bounds__(256) spike_kernel(uint32_t warp_off) {
    uint32_t gwarp = warp_off +
        (uint32_t)((blockIdx.x * blockDim.x + threadIdx.x) >> 5);
    int lane = threadIdx.x & 31;
    if (gwarp >= NWARP_TOT) return;

    uint32_t b = gwarp / (T_ * NPIX);
    uint32_t r_ = gwarp % (T_ * NPIX);
    uint32_t t = r_ / NPIX;
    uint32_t p = r_ % NPIX;

    uint32_t base = gwarp * (uint32_t)CF_;
    const float*  prow  = d_patchs + ((size_t)b * NPIX + p) * CF_;
    const float2* prow2 = reinterpret_cast<const float2*>(prow);

    float s1 = INFINITY, s2 = INFINITY;   // packed top-2 (smallest q wins)

    // q > 0 always (L<0, prw<0); u==0 -> q=+inf -> packed NaN -> fminf drops it
#define FAST_ELEM(prwv, iv, cv) {                                            \
        uint32_t bits = threefry_bits(iv);                                   \
        float u = u_from_bits(bits);                                         \
        float L = __log2f(u);                                                \
        float q = L * (prwv);                                                \
        float qp = __uint_as_float(                                          \
            (__float_as_uint(q) & 0xFFFFFC00u) | (uint32_t)(cv));            \
        s2 = fminf(s2, fmaxf(s1, qp));                                       \
        s1 = fminf(s1, qp);                                                  \
    }

    uint32_t iA = base + (uint32_t)(2 * lane);
    int cA = 2 * lane;
    #pragma unroll
    for (int kk = 0; kk < 4; ++kk) {
        float2 wA = prow2[kk * 64 + lane];
        float2 wB = prow2[kk * 64 + 32 + lane];
        FAST_ELEM(wA.x, iA,       cA);
        FAST_ELEM(wA.y, iA + 1u,  cA + 1);
        FAST_ELEM(wB.x, iA + 64u, cA + 64);
        FAST_ELEM(wB.y, iA + 65u, cA + 65);
        iA += 128u;
        cA += 128;
    }
    {   // slot 8: c = 512 + 2*lane
        float2 w = prow2[256 + lane];
        FAST_ELEM(w.x, iA,      cA);
        FAST_ELEM(w.y, iA + 1u, cA + 1);
    }
    if (lane < 12) {   // tail: c = 576 + 2*lane
        int c = 576 + 2 * lane;
        float2 w = prow2[288 + lane];
        FAST_ELEM(w.x, base + (uint32_t)c,      c);
        FAST_ELEM(w.y, base + (uint32_t)c + 1u, c + 1);
    }
#undef FAST_ELEM

    // warp top-2 min reduce (packed => tie-break automatic)
    #pragma unroll
    for (int off = 16; off; off >>= 1) {
        float o1 = __shfl_down_sync(0xffffffffu, s1, off);
        float o2 = __shfl_down_sync(0xffffffffu, s2, off);
        s2 = fminf(fminf(s2, o2), fmaxf(s1, o1));
        s1 = fminf(s1, o1);
    }

    int safe = 0;
    int widx = 0;
    if (lane == 0) {
        uint32_t i1 = __float_as_uint(s1) & 1023u;
        float prw1 = -prow[i1];                      // = ln2/w1 > 0
        float delta = fmaf(2.6e-7f, prw1,
                      fmaf(1.6e-4f, s1 + s2, 2.0e-5f));
        safe = ((s2 - s1) > delta) ? 1 : 0;
        widx = (int)i1;
    }
    safe = __shfl_sync(0xffffffffu, safe, 0);

    if (!safe) {
        // exact rescan (bit-exact decider), rolled loop
        const float* wrow = d_patch + ((size_t)b * NPIX + p) * CF_;
        float bw = 0.0f, bE = 1.0f;
        int   idx = 0;
        for (int j = 0; j < 19; ++j) {
            int c = lane + 32 * j;
            if (c < CF_) {
                uint32_t bits = threefry_bits(base + (uint32_t)c);
                float E = exp_draw(bits);
                float w = wrow[c];
                if (w * bE > bw * E) { bw = w; bE = E; idx = c; }
            }
        }
        #pragma unroll
        for (int off = 16; off; off >>= 1) {
            float ow = __shfl_down_sync(0xffffffffu, bw, off);
            float oE = __shfl_down_sync(0xffffffffu, bE, off);
            int   oi = __shfl_down_sync(0xffffffffu, idx, off);
            float lhs = ow * bE, rhs = bw * oE;
            if (lhs > rhs || (lhs == rhs && oi < idx)) { bw = ow; bE = oE; idx = oi; }
        }
        if (lane == 0) widx = idx;
    }

    if (lane == 0)
        d_spikes[((size_t)b * NPIX + p) * T_ + t] = widx;
}

// ---------------------------------------------------------------------------
// Kernel 3: normalized recurrence, one warp per (b, pixel), g[128] in regs.
// ---------------------------------------------------------------------------
__global__ void recur_kernel(const float* __restrict__ weights,
                             const float* __restrict__ eps_xy,
                             const float* __restrict__ eps0p,
                             const float* __restrict__ eps_t,
                             const float* __restrict__ h_init,
                             float* __restrict__ out) {
    int gwarp = (blockIdx.x * blockDim.x + threadIdx.x) >> 5;
    int lane  = threadIdx.x & 31;
    if (gwarp >= B_ * NPIX) return;
    int b = gwarp / NPIX, p = gwarp % NPIX;

    float4 g = reinterpret_cast<const float4*>(h_init)[lane];
    float eps0 = eps0p[0];
    const float* epsrow = eps_xy + (size_t)p * KHW;
    const int*   srow   = d_spikes + (size_t)gwarp * T_;

    for (int t = 0; t < T_; ++t) {
        int s = srow[t];
        float4 w = reinterpret_cast<const float4*>(weights + (size_t)s * HN_)[lane];
        float4 wg = make_float4(w.x * g.x, w.y * g.y, w.z * g.z, w.w * g.w);
        float sum = (wg.x + wg.y) + (wg.z + wg.w);
        #pragma unroll
        for (int off = 16; off; off >>= 1)
            sum += __shfl_xor_sync(0xffffffffu, sum, off);

        float eps_sub = epsrow[s % KHW] * (eps_t[t] * eps0);
        float factor  = eps_sub / sum;
        if (!isfinite(factor)) factor = 0.0f;
        float rr = 1.0f / (1.0f + eps_sub);
        g.x = (g.x + wg.x * factor) * rr;
        g.y = (g.y + wg.y * factor) * rr;
        g.z = (g.z + wg.z * factor) * rr;
        g.w = (g.w + wg.w * factor) * rr;
    }

    float* o = out + ((size_t)b * HN_) * NPIX + p;
    o[(lane * 4 + 0) * NPIX] = g.x;
    o[(lane * 4 + 1) * NPIX] = g.y;
    o[(lane * 4 + 2) * NPIX] = g.z;
    o[(lane * 4 + 3) * NPIX] = g.w;
}

// ---------------------------------------------------------------------------
extern "C" void kernel_launch(void* const* d_in, const int* in_sizes, int n_in,
                              void* d_out, int out_size) {
    const float* input   = (const float*)d_in[0];  // [B,C,H,W]
    const float* eps_xy  = (const float*)d_in[1];  // [OH,OW,KH,KW]
    const float* eps0    = (const float*)d_in[2];  // [1]
    const float* eps_t   = (const float*)d_in[3];  // [T]
    const float* weights = (const float*)d_in[4];  // [Cf,Hn]
    const float* h_init  = (const float*)d_in[5];  // [Hn]
    float* out = (float*)d_out;                    // [B,Hn,OH,OW]

    unfold_kernel<<<B_ * NPIX, 256>>>(input);
    spike_kernel<<<NWARP_HALF / 8, 256>>>(0u);
    spike_kernel<<<NWARP_HALF / 8, 256>>>(NWARP_HALF);
    recur_kernel<<<(B_ * NPIX * 32) / 256, 256>>>(weights, eps_xy, eps0,
                                                  eps_t, h_init, out);
}

// round 16
// speedup vs baseline: 1.0813x; 1.0030x over previous
#include <cuda_runtime.h>
#include <cstdint>
#include <math.h>

// Problem constants (fixed by setup_inputs)
#define B_   32
#define C_   24
#define H_   28
#define W_   28
#define OH_  24
#define OW_  24
#define KHW  25
#define CF_  600           // C * KH * KW
#define HN_  128
#define T_   96
#define NPIX (OH_*OW_)     // 576

__device__ float d_patch [B_ * NPIX * CF_];   // [B, OH, OW, Cf]  raw unfolded input
__device__ float d_patchs[B_ * NPIX * CF_];   // prw = -ln2 / w  (negative)
__device__ int   d_spikes[B_ * NPIX * T_];    // [B, OH, OW, T]

#define NWARP_TOT  ((uint32_t)B_ * T_ * NPIX)     // 1,769,472

// ---------------------------------------------------------------------------
// Threefry-2x32-20, key (0, 42). Partitionable path: x = (0, i), out = o0^o1.
// Plain SHF rotate + compiler-scheduled adds: measured-best codegen
// (R8 wide-mul, R13 asm-IMAD adds, R14 runtime-mul rotates all regressed).
// ---------------------------------------------------------------------------
__device__ __forceinline__ uint32_t threefry_bits(uint32_t i) {
    const uint32_t ks1 = 42u;
    const uint32_t ks2 = 0x1BD11BF0u;   // 0 ^ 42 ^ 0x1BD11BDA
    uint32_t x0 = 0u;
    uint32_t x1 = i + ks1;
#define TF_RND(r) { x0 += x1; x1 = __funnelshift_l(x1, x1, (r)) ^ x0; }
    TF_RND(13) TF_RND(15) TF_RND(26) TF_RND(6)
    x0 += ks1;  x1 += ks2 + 1u;
    TF_RND(17) TF_RND(29) TF_RND(16) TF_RND(24)
    x0 += ks2;  x1 += 2u;
    TF_RND(13) TF_RND(15) TF_RND(26) TF_RND(6)
    x1 += ks1 + 3u;
    TF_RND(17) TF_RND(29) TF_RND(16) TF_RND(24)
    x0 += ks1;  x1 += ks2 + 4u;
    TF_RND(13) TF_RND(15) TF_RND(26) TF_RND(6)
    x0 += ks2;  x1 += 5u;
#undef TF_RND
    return x0 ^ x1;
}

// u bits: (bits>>9)|0x3F800000 == umulhi(bits,2^23)+0x3F800000 (bit-exact).
__device__ __forceinline__ float u_from_bits(uint32_t bits) {
    uint32_t ub = __umulhi(bits, 1u << 23) + 0x3F800000u;
    return __uint_as_float(ub) - 1.0f;
}

// ---------------------------------------------------------------------------
// Exact E = -log(u): sign-flipped cephes poly (bit-exact verify path).
// ---------------------------------------------------------------------------
__device__ __forceinline__ float exp_draw(uint32_t bits) {
    float u = u_from_bits(bits);
    uint32_t ix = __float_as_uint(u);
    ix -= 0x3F3504F3u;                       // sqrt(0.5) bits
    int   e  = (int)ix >> 23;
    float m  = __uint_as_float((ix & 0x007FFFFFu) + 0x3F3504F3u);
    float f  = m - 1.0f;
    float z  = f * f;
    float pn = -7.0376836292e-2f;
    pn = fmaf(pn, f,  1.1514610310e-1f);
    pn = fmaf(pn, f, -1.1676998740e-1f);
    pn = fmaf(pn, f,  1.2420140846e-1f);
    pn = fmaf(pn, f, -1.4249322787e-1f);
    pn = fmaf(pn, f,  1.6668057665e-1f);
    pn = fmaf(pn, f, -2.0000714765e-1f);
    pn = fmaf(pn, f,  2.4999993993e-1f);
    pn = fmaf(pn, f, -3.3333331174e-1f);
    float fe = (float)e;
    float q  = fmaf(z * f, pn, fmaf(fe, 2.12194440e-4f, 0.5f * z));
    q = q - f;
    return fmaf(fe, -0.693359375f, q);       // E = -log(u)
}

// ---------------------------------------------------------------------------
// Kernel 1: unfold; writes raw patch AND prw = -ln2/w.
// ---------------------------------------------------------------------------
__global__ void unfold_kernel(const float* __restrict__ input) {
    int row = blockIdx.x;                 // b*NPIX + p
    int b = row / NPIX;
    int p = row % NPIX;
    int x = p / OW_, y = p % OW_;
    float* dst  = d_patch  + (size_t)row * CF_;
    float* dsts = d_patchs + (size_t)row * CF_;
    const float* src = input + ((size_t)b * C_ * H_ + (size_t)x) * W_ + y;
    for (int m = threadIdx.x; m < CF_; m += blockDim.x) {
        int c = m / KHW, k = m % KHW;
        int i = k / 5, j = k % 5;
        float v = src[(c * H_ + i) * W_ + j];
        dst[m]  = v;
        dsts[m] = __fdividef(-0.69314718056f, v);   // prw < 0 (approx; margin covers)
    }
}

// ---------------------------------------------------------------------------
// Kernel 2: spike sampling. Fast path: q = lg2(u) * prw = E/w (argmin),
// index packed into q's low 10 bits so fminf does compare+select+tie-break.
// Margin test vs packed second-best; on failure, exact rescan (bit-exact).
// ---------------------------------------------------------------------------
__global__ void __launch_bounds__(256) spike_kernel(uint32_t warp_off) {
    uint32_t gwarp = warp_off +
        (uint32_t)((blockIdx.x * blockDim.x + threadIdx.x) >> 5);
    int lane = threadIdx.x & 31;
    if (gwarp >= NWARP_TOT) return;

    uint32_t b = gwarp / (T_ * NPIX);
    uint32_t r_ = gwarp % (T_ * NPIX);
    uint32_t t = r_ / NPIX;
    uint32_t p = r_ % NPIX;

    uint32_t base = gwarp * (uint32_t)CF_;
    const float*  prow  = d_patchs + ((size_t)b * NPIX + p) * CF_;
    const float2* prow2 = reinterpret_cast<const float2*>(prow);

    float s1 = INFINITY, s2 = INFINITY;   // packed top-2 (smallest q wins)

    // q > 0 always (L<0, prw<0); u==0 -> q=+inf -> packed NaN -> fminf drops it
#define FAST_ELEM(prwv, iv, cv) {                                            \
        uint32_t bits = threefry_bits(iv);                                   \
        float u = u_from_bits(bits);                                         \
        float L = __log2f(u);                                                \
        float q = L * (prwv);                                                \
        float qp = __uint_as_float(                                          \
            (__float_as_uint(q) & 0xFFFFFC00u) | (uint32_t)(cv));            \
        s2 = fminf(s2, fmaxf(s1, qp));                                       \
        s1 = fminf(s1, qp);                                                  \
    }

    uint32_t iA = base + (uint32_t)(2 * lane);
    int cA = 2 * lane;
    #pragma unroll
    for (int kk = 0; kk < 4; ++kk) {
        float2 wA = prow2[kk * 64 + lane];
        float2 wB = prow2[kk * 64 + 32 + lane];
        FAST_ELEM(wA.x, iA,       cA);
        FAST_ELEM(wA.y, iA + 1u,  cA + 1);
        FAST_ELEM(wB.x, iA + 64u, cA + 64);
        FAST_ELEM(wB.y, iA + 65u, cA + 65);
        iA += 128u;
        cA += 128;
    }
    {   // slot 8: c = 512 + 2*lane
        float2 w = prow2[256 + lane];
        FAST_ELEM(w.x, iA,      cA);
        FAST_ELEM(w.y, iA + 1u, cA + 1);
    }
    if (lane < 12) {   // tail: c = 576 + 2*lane
        int c = 576 + 2 * lane;
        float2 w = prow2[288 + lane];
        FAST_ELEM(w.x, base + (uint32_t)c,      c);
        FAST_ELEM(w.y, base + (uint32_t)c + 1u, c + 1);
    }
#undef FAST_ELEM

    // warp top-2 min reduce (packed => tie-break automatic)
    #pragma unroll
    for (int off = 16; off; off >>= 1) {
        float o1 = __shfl_down_sync(0xffffffffu, s1, off);
        float o2 = __shfl_down_sync(0xffffffffu, s2, off);
        s2 = fminf(fminf(s2, o2), fmaxf(s1, o1));
        s1 = fminf(s1, o1);
    }

    int safe = 0;
    int widx = 0;
    if (lane == 0) {
        uint32_t i1 = __float_as_uint(s1) & 1023u;
        float prw1 = -prow[i1];                      // = ln2/w1 > 0
        float delta = fmaf(2.6e-7f, prw1,
                      fmaf(1.6e-4f, s1 + s2, 2.0e-5f));
        safe = ((s2 - s1) > delta) ? 1 : 0;
        widx = (int)i1;
    }
    safe = __shfl_sync(0xffffffffu, safe, 0);

    if (!safe) {
        // exact rescan (bit-exact decider), rolled loop
        const float* wrow = d_patch + ((size_t)b * NPIX + p) * CF_;
        float bw = 0.0f, bE = 1.0f;
        int   idx = 0;
        for (int j = 0; j < 19; ++j) {
            int c = lane + 32 * j;
            if (c < CF_) {
                uint32_t bits = threefry_bits(base + (uint32_t)c);
                float E = exp_draw(bits);
                float w = wrow[c];
                if (w * bE > bw * E) { bw = w; bE = E; idx = c; }
            }
        }
        #pragma unroll
        for (int off = 16; off; off >>= 1) {
            float ow = __shfl_down_sync(0xffffffffu, bw, off);
            float oE = __shfl_down_sync(0xffffffffu, bE, off);
            int   oi = __shfl_down_sync(0xffffffffu, idx, off);
            float lhs = ow * bE, rhs = bw * oE;
            if (lhs > rhs || (lhs == rhs && oi < idx)) { bw = ow; bE = oE; idx = oi; }
        }
        if (lane == 0) widx = idx;
    }

    if (lane == 0)
        d_spikes[((size_t)b * NPIX + p) * T_ + t] = widx;
}

// ---------------------------------------------------------------------------
// Kernel 3: normalized recurrence, one warp per (b, pixel), g[128] in regs.
// ---------------------------------------------------------------------------
__global__ void recur_kernel(const float* __restrict__ weights,
                             const float* __restrict__ eps_xy,
                             const float* __restrict__ eps0p,
                             const float* __restrict__ eps_t,
                             const float* __restrict__ h_init,
                             float* __restrict__ out) {
    int gwarp = (blockIdx.x * blockDim.x + threadIdx.x) >> 5;
    int lane  = threadIdx.x & 31;
    if (gwarp >= B_ * NPIX) return;
    int b = gwarp / NPIX, p = gwarp % NPIX;

    float4 g = reinterpret_cast<const float4*>(h_init)[lane];
    float eps0 = eps0p[0];
    const float* epsrow = eps_xy + (size_t)p * KHW;
    const int*   srow   = d_spikes + (size_t)gwarp * T_;

    for (int t = 0; t < T_; ++t) {
        int s = srow[t];
        float4 w = reinterpret_cast<const float4*>(weights + (size_t)s * HN_)[lane];
        float4 wg = make_float4(w.x * g.x, w.y * g.y, w.z * g.z, w.w * g.w);
        float sum = (wg.x + wg.y) + (wg.z + wg.w);
        #pragma unroll
        for (int off = 16; off; off >>= 1)
            sum += __shfl_xor_sync(0xffffffffu, sum, off);

        float eps_sub = epsrow[s % KHW] * (eps_t[t] * eps0);
        float factor  = eps_sub / sum;
        if (!isfinite(factor)) factor = 0.0f;
        float rr = 1.0f / (1.0f + eps_sub);
        g.x = (g.x + wg.x * factor) * rr;
        g.y = (g.y + wg.y * factor) * rr;
        g.z = (g.z + wg.z * factor) * rr;
        g.w = (g.w + wg.w * factor) * rr;
    }

    float* o = out + ((size_t)b * HN_) * NPIX + p;
    o[(lane * 4 + 0) * NPIX] = g.x;
    o[(lane * 4 + 1) * NPIX] = g.y;
    o[(lane * 4 + 2) * NPIX] = g.z;
    o[(lane * 4 + 3) * NPIX] = g.w;
}

// ---------------------------------------------------------------------------
extern "C" void kernel_launch(void* const* d_in, const int* in_sizes, int n_in,
                              void* d_out, int out_size) {
    const float* input   = (const float*)d_in[0];  // [B,C,H,W]
    const float* eps_xy  = (const float*)d_in[1];  // [OH,OW,KH,KW]
    const float* eps0    = (const float*)d_in[2];  // [1]
    const float* eps_t   = (const float*)d_in[3];  // [T]
    const float* weights = (const float*)d_in[4];  // [Cf,Hn]
    const float* h_init  = (const float*)d_in[5];  // [Hn]
    float* out = (float*)d_out;                    // [B,Hn,OH,OW]

    unfold_kernel<<<B_ * NPIX, 256>>>(input);
    spike_kernel<<<NWARP_TOT / 8, 256>>>(0u);   // single launch (split no longer needed)
    recur_kernel<<<(B_ * NPIX * 32) / 256, 256>>>(weights, eps_xy, eps0,
                                                  eps_t, h_init, out);
}